// round 1
// baseline (speedup 1.0000x reference)
#include <cuda_runtime.h>
#include <math.h>

// ---------------- problem constants ----------------
#define BATCH   2
#define SEQLEN  2048
#define DMODEL  4096
#define NHEADS  32
#define NKV     8
#define HD      128
#define QDIM    (NHEADS * HD)            // 4096
#define KVDIM   (NKV * HD)               // 1024
#define QKVDIM  (QDIM + 2 * KVDIM)       // 6144
#define MROWS   (BATCH * SEQLEN)         // 4096
#define GROUP   (NHEADS / NKV)           // 4

// ---------------- scratch (device globals: allocation-free) ----------------
__device__ float g_qkv[(size_t)MROWS * QKVDIM];   // ~100 MB
__device__ float g_attn[(size_t)MROWS * DMODEL];  // ~67 MB

// ============================================================
// SGEMM: C[M,N] = A[M,K] @ B[N,K]^T + bias[N]
// 128x128 block tile, BK=16, 8x8 per thread, 256 threads
// ============================================================
#define GBM 128
#define GBN 128
#define GBK 16

__global__ __launch_bounds__(256) void sgemm_bias_kernel(
    const float* __restrict__ A, const float* __restrict__ B,
    const float* __restrict__ bias, float* __restrict__ C,
    int M, int N, int K)
{
    __shared__ float As[GBK][GBM + 4];
    __shared__ float Bs[GBK][GBN + 4];

    const int tid = threadIdx.x;
    const int bm  = blockIdx.y * GBM;
    const int bn  = blockIdx.x * GBN;
    const int ty  = tid >> 4;    // 0..15
    const int tx  = tid & 15;    // 0..15

    float acc[8][8];
    #pragma unroll
    for (int i = 0; i < 8; i++)
        #pragma unroll
        for (int j = 0; j < 8; j++) acc[i][j] = 0.f;

    for (int k0 = 0; k0 < K; k0 += GBK) {
        // load A tile (128 rows x 16 k) and B tile (128 n-rows x 16 k), transposed into smem
        #pragma unroll
        for (int l = 0; l < 2; l++) {
            int idx = tid + l * 256;       // 0..511
            int row = idx >> 2;            // 0..127
            int kq  = (idx & 3) << 2;      // 0,4,8,12
            float4 a = *(const float4*)(A + (size_t)(bm + row) * K + k0 + kq);
            As[kq + 0][row] = a.x; As[kq + 1][row] = a.y;
            As[kq + 2][row] = a.z; As[kq + 3][row] = a.w;
            float4 b = *(const float4*)(B + (size_t)(bn + row) * K + k0 + kq);
            Bs[kq + 0][row] = b.x; Bs[kq + 1][row] = b.y;
            Bs[kq + 2][row] = b.z; Bs[kq + 3][row] = b.w;
        }
        __syncthreads();

        #pragma unroll
        for (int k = 0; k < GBK; k++) {
            float4 a0 = *(float4*)&As[k][ty * 8];
            float4 a1 = *(float4*)&As[k][ty * 8 + 4];
            float4 b0 = *(float4*)&Bs[k][tx * 8];
            float4 b1 = *(float4*)&Bs[k][tx * 8 + 4];
            float av[8] = {a0.x, a0.y, a0.z, a0.w, a1.x, a1.y, a1.z, a1.w};
            float bv[8] = {b0.x, b0.y, b0.z, b0.w, b1.x, b1.y, b1.z, b1.w};
            #pragma unroll
            for (int i = 0; i < 8; i++)
                #pragma unroll
                for (int j = 0; j < 8; j++)
                    acc[i][j] += av[i] * bv[j];
        }
        __syncthreads();
    }

    // epilogue with fused bias
    float bv0[8];
    #pragma unroll
    for (int j = 0; j < 8; j++) bv0[j] = bias[bn + tx * 8 + j];

    #pragma unroll
    for (int i = 0; i < 8; i++) {
        float* crow = C + (size_t)(bm + ty * 8 + i) * N + bn + tx * 8;
        float4 o0, o1;
        o0.x = acc[i][0] + bv0[0]; o0.y = acc[i][1] + bv0[1];
        o0.z = acc[i][2] + bv0[2]; o0.w = acc[i][3] + bv0[3];
        o1.x = acc[i][4] + bv0[4]; o1.y = acc[i][5] + bv0[5];
        o1.z = acc[i][6] + bv0[6]; o1.w = acc[i][7] + bv0[7];
        *(float4*)(crow)     = o0;
        *(float4*)(crow + 4) = o1;
    }
}

// ============================================================
// RoPE: in-place on q (32 heads) and k (8 heads) of g_qkv.
// One thread per (b, s, head, freq-pair).
// ============================================================
__global__ void rope_kernel(float* __restrict__ qkv)
{
    int idx = blockIdx.x * blockDim.x + threadIdx.x;
    // total = BATCH*SEQLEN*(NHEADS+NKV)*(HD/2) = 10485760
    int p = idx & 63;            // freq pair 0..63
    idx >>= 6;
    int head = idx % (NHEADS + NKV);
    idx /= (NHEADS + NKV);
    int s = idx % SEQLEN;
    int b = idx / SEQLEN;
    if (b >= BATCH) return;

    int col = (head < NHEADS) ? head * HD : QDIM + (head - NHEADS) * HD;

    float inv_freq = powf(10000.0f, -(float)(2 * p) / (float)HD);
    float ang = (float)s * inv_freq;
    float c, sn;
    sincosf(ang, &sn, &c);

    float* base = qkv + (size_t)(b * SEQLEN + s) * QKVDIM + col + 2 * p;
    float xr = base[0];
    float xi = base[1];
    base[0] = xr * c - xi * sn;
    base[1] = xr * sn + xi * c;
}

// ============================================================
// Flash attention (fp32, online softmax, causal).
// Block: 256 threads (16x16). Tile: 64 queries x 64 keys.
// Thread (ty,tx): 4 query rows (ty*4+i), score cols tx*4+j,
//                 output hd cols tx*8+j.
// Output layout: [b, s, h, d] flattened = [MROWS, DMODEL].
// ============================================================
#define FBM 64
#define FBN 64
#define KS_STRIDE 132   // padded, 16B-aligned row stride
#define PS_STRIDE 68

__global__ __launch_bounds__(256) void flash_attn_kernel(
    const float* __restrict__ qkv, float* __restrict__ outa)
{
    extern __shared__ float sm[];
    float* Qs = sm;                       // [64][128]
    float* Ks = Qs + 64 * 128;            // [64][132]
    float* Vs = Ks + 64 * KS_STRIDE;      // [64][128]
    float* Ps = Vs + 64 * 128;            // [64][68]

    const int tid = threadIdx.x;
    const int tx = tid & 15, ty = tid >> 4;
    const int b = blockIdx.z, h = blockIdx.y, qt = blockIdx.x;
    const int kvh = h >> 2;  // GROUP = 4
    const int q0 = qt * FBM;

    const float* qbase = qkv + (size_t)b * SEQLEN * QKVDIM + h * HD;
    const float* kbase = qkv + (size_t)b * SEQLEN * QKVDIM + QDIM + kvh * HD;
    const float* vbase = qkv + (size_t)b * SEQLEN * QKVDIM + QDIM + KVDIM + kvh * HD;

    // load Q tile: 64 rows x 128 -> 2048 float4, 8 per thread
    #pragma unroll
    for (int l = 0; l < 8; l++) {
        int fidx = tid + l * 256;
        int r = fidx >> 5;
        int d4 = (fidx & 31) << 2;
        *(float4*)&Qs[r * 128 + d4] =
            *(const float4*)(qbase + (size_t)(q0 + r) * QKVDIM + d4);
    }

    const float SCALE = 0.08838834764831845f;  // 1/sqrt(128)
    float m_i[4], l_i[4], O[4][8];
    #pragma unroll
    for (int i = 0; i < 4; i++) {
        m_i[i] = -3.0e38f;
        l_i[i] = 0.f;
        #pragma unroll
        for (int j = 0; j < 8; j++) O[i][j] = 0.f;
    }

    for (int t = 0; t <= qt; t++) {
        const int k0 = t * FBN;
        __syncthreads();  // protect prev-iter smem reads (also covers Q load)

        // load K and V tiles
        #pragma unroll
        for (int l = 0; l < 8; l++) {
            int fidx = tid + l * 256;
            int r = fidx >> 5;
            int d4 = (fidx & 31) << 2;
            *(float4*)&Ks[r * KS_STRIDE + d4] =
                *(const float4*)(kbase + (size_t)(k0 + r) * QKVDIM + d4);
            *(float4*)&Vs[r * 128 + d4] =
                *(const float4*)(vbase + (size_t)(k0 + r) * QKVDIM + d4);
        }
        __syncthreads();

        // scores: S[4][4] = Q[4 rows] . K[4 cols]
        float acc[4][4];
        #pragma unroll
        for (int i = 0; i < 4; i++)
            #pragma unroll
            for (int j = 0; j < 4; j++) acc[i][j] = 0.f;

        #pragma unroll 4
        for (int d = 0; d < HD; d += 4) {
            float4 qv[4], kv[4];
            #pragma unroll
            for (int i = 0; i < 4; i++)
                qv[i] = *(float4*)&Qs[(ty * 4 + i) * 128 + d];
            #pragma unroll
            for (int j = 0; j < 4; j++)
                kv[j] = *(float4*)&Ks[(tx * 4 + j) * KS_STRIDE + d];
            #pragma unroll
            for (int i = 0; i < 4; i++)
                #pragma unroll
                for (int j = 0; j < 4; j++) {
                    acc[i][j] += qv[i].x * kv[j].x;
                    acc[i][j] += qv[i].y * kv[j].y;
                    acc[i][j] += qv[i].z * kv[j].z;
                    acc[i][j] += qv[i].w * kv[j].w;
                }
        }

        // scale + causal mask (only diagonal tile needs masking)
        #pragma unroll
        for (int i = 0; i < 4; i++)
            #pragma unroll
            for (int j = 0; j < 4; j++) {
                acc[i][j] *= SCALE;
                if (t == qt && (k0 + tx * 4 + j) > (q0 + ty * 4 + i))
                    acc[i][j] = -3.0e38f;
            }

        // online softmax per query row
        #pragma unroll
        for (int i = 0; i < 4; i++) {
            float rmax = fmaxf(fmaxf(acc[i][0], acc[i][1]), fmaxf(acc[i][2], acc[i][3]));
            #pragma unroll
            for (int ofs = 8; ofs > 0; ofs >>= 1)
                rmax = fmaxf(rmax, __shfl_xor_sync(0xffffffffu, rmax, ofs));
            float mnew = fmaxf(m_i[i], rmax);

            float p[4], psum = 0.f;
            #pragma unroll
            for (int j = 0; j < 4; j++) {
                p[j] = expf(acc[i][j] - mnew);
                psum += p[j];
            }
            #pragma unroll
            for (int ofs = 8; ofs > 0; ofs >>= 1)
                psum += __shfl_xor_sync(0xffffffffu, psum, ofs);

            float corr = expf(m_i[i] - mnew);
            l_i[i] = l_i[i] * corr + psum;
            m_i[i] = mnew;
            #pragma unroll
            for (int j = 0; j < 8; j++) O[i][j] *= corr;

            #pragma unroll
            for (int j = 0; j < 4; j++)
                Ps[(ty * 4 + i) * PS_STRIDE + tx * 4 + j] = p[j];
        }
        __syncthreads();

        // O += P @ V
        #pragma unroll 4
        for (int n = 0; n < FBN; n++) {
            float4 v0 = *(float4*)&Vs[n * 128 + tx * 8];
            float4 v1 = *(float4*)&Vs[n * 128 + tx * 8 + 4];
            #pragma unroll
            for (int i = 0; i < 4; i++) {
                float pv = Ps[(ty * 4 + i) * PS_STRIDE + n];
                O[i][0] += pv * v0.x; O[i][1] += pv * v0.y;
                O[i][2] += pv * v0.z; O[i][3] += pv * v0.w;
                O[i][4] += pv * v1.x; O[i][5] += pv * v1.y;
                O[i][6] += pv * v1.z; O[i][7] += pv * v1.w;
            }
        }
    }

    // write output: [b, s, h, d]
    #pragma unroll
    for (int i = 0; i < 4; i++) {
        float inv = 1.0f / l_i[i];
        size_t row = (size_t)(b * SEQLEN + q0 + ty * 4 + i);
        float* orow = outa + row * DMODEL + h * HD + tx * 8;
        float4 o0, o1;
        o0.x = O[i][0] * inv; o0.y = O[i][1] * inv;
        o0.z = O[i][2] * inv; o0.w = O[i][3] * inv;
        o1.x = O[i][4] * inv; o1.y = O[i][5] * inv;
        o1.z = O[i][6] * inv; o1.w = O[i][7] * inv;
        *(float4*)(orow)     = o0;
        *(float4*)(orow + 4) = o1;
    }
}

// ============================================================
// launch
// ============================================================
extern "C" void kernel_launch(void* const* d_in, const int* in_sizes, int n_in,
                              void* d_out, int out_size)
{
    (void)in_sizes; (void)n_in; (void)out_size;
    const float* x      = (const float*)d_in[0];
    const float* w_qkv  = (const float*)d_in[1];
    const float* b_qkv  = (const float*)d_in[2];
    const float* w_o    = (const float*)d_in[3];
    const float* b_o    = (const float*)d_in[4];
    float* out = (float*)d_out;

    float* qkv = nullptr;
    float* attn = nullptr;
    cudaGetSymbolAddress((void**)&qkv, g_qkv);
    cudaGetSymbolAddress((void**)&attn, g_attn);

    // 1) QKV projection: [4096,6144] = x @ w_qkv^T + b_qkv
    sgemm_bias_kernel<<<dim3(QKVDIM / GBN, MROWS / GBM), 256>>>(
        x, w_qkv, b_qkv, qkv, MROWS, QKVDIM, DMODEL);

    // 2) RoPE on q and k (in place)
    {
        int total = BATCH * SEQLEN * (NHEADS + NKV) * (HD / 2);
        rope_kernel<<<total / 256, 256>>>(qkv);
    }

    // 3) flash attention -> g_attn [b,s,h,d]
    {
        const int smem = (64 * 128 + 64 * KS_STRIDE + 64 * 128 + 64 * PS_STRIDE) * 4;
        cudaFuncSetAttribute(flash_attn_kernel,
                             cudaFuncAttributeMaxDynamicSharedMemorySize, smem);
        flash_attn_kernel<<<dim3(SEQLEN / FBM, NHEADS, BATCH), 256, smem>>>(qkv, attn);
    }

    // 4) output projection: out = attn @ w_o^T + b_o
    sgemm_bias_kernel<<<dim3(DMODEL / GBN, MROWS / GBM), 256>>>(
        attn, w_o, b_o, out, MROWS, DMODEL, DMODEL);
}

// round 4
// speedup vs baseline: 1.4677x; 1.4677x over previous
#include <cuda_runtime.h>
#include <cuda_bf16.h>
#include <math.h>
#include <stdint.h>

// ---------------- problem constants ----------------
#define BATCH   2
#define SEQLEN  2048
#define DMODEL  4096
#define NHEADS  32
#define NKV     8
#define HD      128
#define QDIM    (NHEADS * HD)            // 4096
#define KVDIM   (NKV * HD)               // 1024
#define QKVDIM  (QDIM + 2 * KVDIM)       // 6144
#define MROWS   (BATCH * SEQLEN)         // 4096
#define GROUP   (NHEADS / NKV)           // 4

// ---------------- scratch (device globals: allocation-free) ----------------
__device__ float g_qkv[(size_t)MROWS * QKVDIM];
__device__ float g_attn[(size_t)MROWS * DMODEL];
__device__ __nv_bfloat16 g_xh[(size_t)MROWS * DMODEL];
__device__ __nv_bfloat16 g_xl[(size_t)MROWS * DMODEL];
__device__ __nv_bfloat16 g_wqkvh[(size_t)QKVDIM * DMODEL];
__device__ __nv_bfloat16 g_wqkvl[(size_t)QKVDIM * DMODEL];
__device__ __nv_bfloat16 g_woh[(size_t)DMODEL * DMODEL];
__device__ __nv_bfloat16 g_wol[(size_t)DMODEL * DMODEL];
__device__ __nv_bfloat16 g_ah[(size_t)MROWS * DMODEL];
__device__ __nv_bfloat16 g_al[(size_t)MROWS * DMODEL];

// ---------------- helpers ----------------
__device__ __forceinline__ uint32_t smem_to_u32(const void* smem_ptr) {
    uint32_t addr;
    asm("{ .reg .u64 tmp; cvta.to.shared.u64 tmp, %1; cvt.u32.u64 %0, tmp; }"
        : "=r"(addr) : "l"(smem_ptr));
    return addr;
}
__device__ __forceinline__ void cp_async16(uint32_t dst, const void* src) {
    asm volatile("cp.async.cg.shared.global [%0], [%1], 16;\n"
                 :: "r"(dst), "l"(src));
}
__device__ __forceinline__ void cp_commit() {
    asm volatile("cp.async.commit_group;\n" ::: "memory");
}
__device__ __forceinline__ void cp_wait1() {
    asm volatile("cp.async.wait_group 1;\n" ::: "memory");
}
__device__ __forceinline__ void ldm_x4(uint32_t* r, uint32_t a) {
    asm volatile("ldmatrix.sync.aligned.m8n8.x4.shared.b16 {%0,%1,%2,%3}, [%4];"
                 : "=r"(r[0]), "=r"(r[1]), "=r"(r[2]), "=r"(r[3]) : "r"(a));
}
__device__ __forceinline__ void mma_bf16(float* c, const uint32_t* a,
                                         uint32_t b0, uint32_t b1) {
    asm volatile(
        "mma.sync.aligned.m16n8k16.row.col.f32.bf16.bf16.f32 "
        "{%0,%1,%2,%3}, {%4,%5,%6,%7}, {%8,%9}, {%0,%1,%2,%3};"
        : "+f"(c[0]), "+f"(c[1]), "+f"(c[2]), "+f"(c[3])
        : "r"(a[0]), "r"(a[1]), "r"(a[2]), "r"(a[3]), "r"(b0), "r"(b1));
}

// ============================================================
// HMMA GEMM: C[M,N] = Ahi/lo[M,K] @ (Bhi/lo[N,K])^T + bias[N]
// CTA tile 128x256, BK=32, 8 warps (warp tile 64x64),
// bf16x3 emulation (AhBh + AlBh + AhBl), fp32 accum in regs.
// ============================================================
#define HBM 128
#define HBN 256
#define HBK 32
#define ROWB 80                  // padded row stride in bytes (32 bf16 + 8 pad)
#define OFF_AH 0
#define OFF_AL 10240
#define OFF_BH 20480
#define OFF_BL 40960
#define STAGE_B 61440
#define HSMEM (2 * STAGE_B)      // 122880 bytes

__device__ __forceinline__ void gemm_load_stage(
    const __nv_bfloat16* __restrict__ Ah, const __nv_bfloat16* __restrict__ Al,
    const __nv_bfloat16* __restrict__ Bh, const __nv_bfloat16* __restrict__ Bl,
    uint32_t sbase, int bm, int bn, int k0, int K, int tid)
{
    // A: 128 rows x 32 bf16 per half -> 512 x 16B chunks per half
    #pragma unroll
    for (int l = 0; l < 2; l++) {
        int u = tid + l * 256;
        int r = u >> 2, g = u & 3;
        size_t goff = (size_t)(bm + r) * K + k0 + g * 8;
        cp_async16(sbase + OFF_AH + r * ROWB + g * 16, Ah + goff);
        cp_async16(sbase + OFF_AL + r * ROWB + g * 16, Al + goff);
    }
    // B: 256 rows x 32 bf16 per half -> 1024 x 16B chunks per half
    #pragma unroll
    for (int l = 0; l < 4; l++) {
        int u = tid + l * 256;
        int r = u >> 2, g = u & 3;
        size_t goff = (size_t)(bn + r) * K + k0 + g * 8;
        cp_async16(sbase + OFF_BH + r * ROWB + g * 16, Bh + goff);
        cp_async16(sbase + OFF_BL + r * ROWB + g * 16, Bl + goff);
    }
}

__global__ __launch_bounds__(256) void hmma_gemm_kernel(
    const __nv_bfloat16* __restrict__ Ah, const __nv_bfloat16* __restrict__ Al,
    const __nv_bfloat16* __restrict__ Bh, const __nv_bfloat16* __restrict__ Bl,
    const float* __restrict__ bias, float* __restrict__ C,
    int M, int N, int K)
{
    extern __shared__ char smem[];
    const uint32_t sb = smem_to_u32(smem);
    const int tid = threadIdx.x;
    const int lane = tid & 31, wid = tid >> 5;
    const int wm = wid & 1;        // 2 warp rows  (64 m each)
    const int wn = wid >> 1;       // 4 warp cols  (64 n each)
    const int bm = blockIdx.y * HBM;
    const int bn = blockIdx.x * HBN;

    float acc[4][8][4];
    #pragma unroll
    for (int i = 0; i < 4; i++)
        #pragma unroll
        for (int j = 0; j < 8; j++)
            #pragma unroll
            for (int v = 0; v < 4; v++) acc[i][j][v] = 0.f;

    const int NC = K / HBK;

    gemm_load_stage(Ah, Al, Bh, Bl, sb, bm, bn, 0, K, tid);
    cp_commit();

    for (int c = 0; c < NC; c++) {
        if (c + 1 < NC)
            gemm_load_stage(Ah, Al, Bh, Bl, sb + ((c + 1) & 1) * STAGE_B,
                            bm, bn, (c + 1) * HBK, K, tid);
        cp_commit();
        cp_wait1();
        __syncthreads();

        const uint32_t base = sb + (c & 1) * STAGE_B;
        #pragma unroll
        for (int ks = 0; ks < 2; ks++) {
            const int kb = ks * 32 + ((lane >> 4) * 16);
            uint32_t a_addr = base + OFF_AH + (wm * 64 + (lane & 15)) * ROWB + kb;
            uint32_t b_addr = base + OFF_BH + (wn * 64 + (lane & 15)) * ROWB + kb;

            uint32_t A0[4][4], A1[4][4], B0[4][4];
            #pragma unroll
            for (int mt = 0; mt < 4; mt++) ldm_x4(A0[mt], a_addr + mt * 16 * ROWB);
            #pragma unroll
            for (int nt = 0; nt < 4; nt++) ldm_x4(B0[nt], b_addr + nt * 16 * ROWB);

            // pass 1: Ah * Bh
            #pragma unroll
            for (int mt = 0; mt < 4; mt++)
                #pragma unroll
                for (int nt = 0; nt < 4; nt++) {
                    mma_bf16(acc[mt][2 * nt],     A0[mt], B0[nt][0], B0[nt][2]);
                    mma_bf16(acc[mt][2 * nt + 1], A0[mt], B0[nt][1], B0[nt][3]);
                }
            // pass 2: Al * Bh
            #pragma unroll
            for (int mt = 0; mt < 4; mt++)
                ldm_x4(A1[mt], a_addr + (OFF_AL - OFF_AH) + mt * 16 * ROWB);
            #pragma unroll
            for (int mt = 0; mt < 4; mt++)
                #pragma unroll
                for (int nt = 0; nt < 4; nt++) {
                    mma_bf16(acc[mt][2 * nt],     A1[mt], B0[nt][0], B0[nt][2]);
                    mma_bf16(acc[mt][2 * nt + 1], A1[mt], B0[nt][1], B0[nt][3]);
                }
            // pass 3: Ah * Bl
            #pragma unroll
            for (int nt = 0; nt < 4; nt++)
                ldm_x4(B0[nt], b_addr + (OFF_BL - OFF_BH) + nt * 16 * ROWB);
            #pragma unroll
            for (int mt = 0; mt < 4; mt++)
                #pragma unroll
                for (int nt = 0; nt < 4; nt++) {
                    mma_bf16(acc[mt][2 * nt],     A0[mt], B0[nt][0], B0[nt][2]);
                    mma_bf16(acc[mt][2 * nt + 1], A0[mt], B0[nt][1], B0[nt][3]);
                }
        }
        __syncthreads();
    }

    // epilogue: fused bias, float2 stores
    #pragma unroll
    for (int mt = 0; mt < 4; mt++) {
        const int row0 = bm + wm * 64 + mt * 16 + (lane >> 2);
        #pragma unroll
        for (int nt = 0; nt < 8; nt++) {
            const int col = bn + wn * 64 + nt * 8 + (lane & 3) * 2;
            const float b0 = bias[col], b1 = bias[col + 1];
            float2 v0 = make_float2(acc[mt][nt][0] + b0, acc[mt][nt][1] + b1);
            float2 v1 = make_float2(acc[mt][nt][2] + b0, acc[mt][nt][3] + b1);
            *(float2*)(C + (size_t)row0 * N + col) = v0;
            *(float2*)(C + (size_t)(row0 + 8) * N + col) = v1;
        }
    }
}

// ============================================================
// fp32 -> bf16 hi/lo split
// ============================================================
__global__ void split_bf16_kernel(const float* __restrict__ src,
                                  __nv_bfloat16* __restrict__ hi,
                                  __nv_bfloat16* __restrict__ lo, int n4)
{
    int i = blockIdx.x * blockDim.x + threadIdx.x;
    if (i >= n4) return;
    float4 v = ((const float4*)src)[i];
    __nv_bfloat16 h0 = __float2bfloat16(v.x);
    __nv_bfloat16 h1 = __float2bfloat16(v.y);
    __nv_bfloat16 h2 = __float2bfloat16(v.z);
    __nv_bfloat16 h3 = __float2bfloat16(v.w);
    __nv_bfloat16 l0 = __float2bfloat16(v.x - __bfloat162float(h0));
    __nv_bfloat16 l1 = __float2bfloat16(v.y - __bfloat162float(h1));
    __nv_bfloat16 l2 = __float2bfloat16(v.z - __bfloat162float(h2));
    __nv_bfloat16 l3 = __float2bfloat16(v.w - __bfloat162float(h3));
    __nv_bfloat162* hp = (__nv_bfloat162*)hi;
    __nv_bfloat162* lp = (__nv_bfloat162*)lo;
    hp[2 * i]     = __nv_bfloat162(h0, h1);
    hp[2 * i + 1] = __nv_bfloat162(h2, h3);
    lp[2 * i]     = __nv_bfloat162(l0, l1);
    lp[2 * i + 1] = __nv_bfloat162(l2, l3);
}

// ============================================================
// RoPE: in-place on q (32 heads) and k (8 heads) of g_qkv.
// ============================================================
__global__ void rope_kernel(float* __restrict__ qkv)
{
    int idx = blockIdx.x * blockDim.x + threadIdx.x;
    int p = idx & 63;
    idx >>= 6;
    int head = idx % (NHEADS + NKV);
    idx /= (NHEADS + NKV);
    int s = idx % SEQLEN;
    int b = idx / SEQLEN;
    if (b >= BATCH) return;

    int col = (head < NHEADS) ? head * HD : QDIM + (head - NHEADS) * HD;

    float inv_freq = powf(10000.0f, -(float)(2 * p) / (float)HD);
    float ang = (float)s * inv_freq;
    float c, sn;
    sincosf(ang, &sn, &c);

    float* base = qkv + (size_t)(b * SEQLEN + s) * QKVDIM + col + 2 * p;
    float xr = base[0];
    float xi = base[1];
    base[0] = xr * c - xi * sn;
    base[1] = xr * sn + xi * c;
}

// ============================================================
// Flash attention (fp32, online softmax, causal)
// ============================================================
#define FBM 64
#define FBN 64
#define KS_STRIDE 132
#define PS_STRIDE 68

__global__ __launch_bounds__(256) void flash_attn_kernel(
    const float* __restrict__ qkv, float* __restrict__ outa)
{
    extern __shared__ float sm[];
    float* Qs = sm;
    float* Ks = Qs + 64 * 128;
    float* Vs = Ks + 64 * KS_STRIDE;
    float* Ps = Vs + 64 * 128;

    const int tid = threadIdx.x;
    const int tx = tid & 15, ty = tid >> 4;
    const int b = blockIdx.z, h = blockIdx.y, qt = blockIdx.x;
    const int kvh = h >> 2;
    const int q0 = qt * FBM;

    const float* qbase = qkv + (size_t)b * SEQLEN * QKVDIM + h * HD;
    const float* kbase = qkv + (size_t)b * SEQLEN * QKVDIM + QDIM + kvh * HD;
    const float* vbase = qkv + (size_t)b * SEQLEN * QKVDIM + QDIM + KVDIM + kvh * HD;

    #pragma unroll
    for (int l = 0; l < 8; l++) {
        int fidx = tid + l * 256;
        int r = fidx >> 5;
        int d4 = (fidx & 31) << 2;
        *(float4*)&Qs[r * 128 + d4] =
            *(const float4*)(qbase + (size_t)(q0 + r) * QKVDIM + d4);
    }

    const float SCALE = 0.08838834764831845f;
    float m_i[4], l_i[4], O[4][8];
    #pragma unroll
    for (int i = 0; i < 4; i++) {
        m_i[i] = -3.0e38f;
        l_i[i] = 0.f;
        #pragma unroll
        for (int j = 0; j < 8; j++) O[i][j] = 0.f;
    }

    for (int t = 0; t <= qt; t++) {
        const int k0 = t * FBN;
        __syncthreads();

        #pragma unroll
        for (int l = 0; l < 8; l++) {
            int fidx = tid + l * 256;
            int r = fidx >> 5;
            int d4 = (fidx & 31) << 2;
            *(float4*)&Ks[r * KS_STRIDE + d4] =
                *(const float4*)(kbase + (size_t)(k0 + r) * QKVDIM + d4);
            *(float4*)&Vs[r * 128 + d4] =
                *(const float4*)(vbase + (size_t)(k0 + r) * QKVDIM + d4);
        }
        __syncthreads();

        float acc[4][4];
        #pragma unroll
        for (int i = 0; i < 4; i++)
            #pragma unroll
            for (int j = 0; j < 4; j++) acc[i][j] = 0.f;

        #pragma unroll 4
        for (int d = 0; d < HD; d += 4) {
            float4 qv[4], kv[4];
            #pragma unroll
            for (int i = 0; i < 4; i++)
                qv[i] = *(float4*)&Qs[(ty * 4 + i) * 128 + d];
            #pragma unroll
            for (int j = 0; j < 4; j++)
                kv[j] = *(float4*)&Ks[(tx * 4 + j) * KS_STRIDE + d];
            #pragma unroll
            for (int i = 0; i < 4; i++)
                #pragma unroll
                for (int j = 0; j < 4; j++) {
                    acc[i][j] += qv[i].x * kv[j].x;
                    acc[i][j] += qv[i].y * kv[j].y;
                    acc[i][j] += qv[i].z * kv[j].z;
                    acc[i][j] += qv[i].w * kv[j].w;
                }
        }

        #pragma unroll
        for (int i = 0; i < 4; i++)
            #pragma unroll
            for (int j = 0; j < 4; j++) {
                acc[i][j] *= SCALE;
                if (t == qt && (k0 + tx * 4 + j) > (q0 + ty * 4 + i))
                    acc[i][j] = -3.0e38f;
            }

        #pragma unroll
        for (int i = 0; i < 4; i++) {
            float rmax = fmaxf(fmaxf(acc[i][0], acc[i][1]), fmaxf(acc[i][2], acc[i][3]));
            #pragma unroll
            for (int ofs = 8; ofs > 0; ofs >>= 1)
                rmax = fmaxf(rmax, __shfl_xor_sync(0xffffffffu, rmax, ofs));
            float mnew = fmaxf(m_i[i], rmax);

            float p[4], psum = 0.f;
            #pragma unroll
            for (int j = 0; j < 4; j++) {
                p[j] = expf(acc[i][j] - mnew);
                psum += p[j];
            }
            #pragma unroll
            for (int ofs = 8; ofs > 0; ofs >>= 1)
                psum += __shfl_xor_sync(0xffffffffu, psum, ofs);

            float corr = expf(m_i[i] - mnew);
            l_i[i] = l_i[i] * corr + psum;
            m_i[i] = mnew;
            #pragma unroll
            for (int j = 0; j < 8; j++) O[i][j] *= corr;

            #pragma unroll
            for (int j = 0; j < 4; j++)
                Ps[(ty * 4 + i) * PS_STRIDE + tx * 4 + j] = p[j];
        }
        __syncthreads();

        #pragma unroll 4
        for (int n = 0; n < FBN; n++) {
            float4 v0 = *(float4*)&Vs[n * 128 + tx * 8];
            float4 v1 = *(float4*)&Vs[n * 128 + tx * 8 + 4];
            #pragma unroll
            for (int i = 0; i < 4; i++) {
                float pv = Ps[(ty * 4 + i) * PS_STRIDE + n];
                O[i][0] += pv * v0.x; O[i][1] += pv * v0.y;
                O[i][2] += pv * v0.z; O[i][3] += pv * v0.w;
                O[i][4] += pv * v1.x; O[i][5] += pv * v1.y;
                O[i][6] += pv * v1.z; O[i][7] += pv * v1.w;
            }
        }
    }

    #pragma unroll
    for (int i = 0; i < 4; i++) {
        float inv = 1.0f / l_i[i];
        size_t row = (size_t)(b * SEQLEN + q0 + ty * 4 + i);
        float* orow = outa + row * DMODEL + h * HD + tx * 8;
        float4 o0, o1;
        o0.x = O[i][0] * inv; o0.y = O[i][1] * inv;
        o0.z = O[i][2] * inv; o0.w = O[i][3] * inv;
        o1.x = O[i][4] * inv; o1.y = O[i][5] * inv;
        o1.z = O[i][6] * inv; o1.w = O[i][7] * inv;
        *(float4*)(orow)     = o0;
        *(float4*)(orow + 4) = o1;
    }
}

// ============================================================
// launch
// ============================================================
extern "C" void kernel_launch(void* const* d_in, const int* in_sizes, int n_in,
                              void* d_out, int out_size)
{
    (void)in_sizes; (void)n_in; (void)out_size;
    const float* x      = (const float*)d_in[0];
    const float* w_qkv  = (const float*)d_in[1];
    const float* b_qkv  = (const float*)d_in[2];
    const float* w_o    = (const float*)d_in[3];
    const float* b_o    = (const float*)d_in[4];
    float* out = (float*)d_out;

    float *qkv, *attn;
    __nv_bfloat16 *xh, *xl, *wqh, *wql, *woh, *wol, *ah, *al;
    cudaGetSymbolAddress((void**)&qkv,  g_qkv);
    cudaGetSymbolAddress((void**)&attn, g_attn);
    cudaGetSymbolAddress((void**)&xh,  g_xh);
    cudaGetSymbolAddress((void**)&xl,  g_xl);
    cudaGetSymbolAddress((void**)&wqh, g_wqkvh);
    cudaGetSymbolAddress((void**)&wql, g_wqkvl);
    cudaGetSymbolAddress((void**)&woh, g_woh);
    cudaGetSymbolAddress((void**)&wol, g_wol);
    cudaGetSymbolAddress((void**)&ah,  g_ah);
    cudaGetSymbolAddress((void**)&al,  g_al);

    cudaFuncSetAttribute(hmma_gemm_kernel,
                         cudaFuncAttributeMaxDynamicSharedMemorySize, HSMEM);

    // 0) split inputs to bf16 hi/lo
    {
        int n4 = (MROWS * DMODEL) / 4;
        split_bf16_kernel<<<n4 / 256, 256>>>(x, xh, xl, n4);
        int w4 = (QKVDIM * DMODEL) / 4;
        split_bf16_kernel<<<w4 / 256, 256>>>(w_qkv, wqh, wql, w4);
        int o4 = (DMODEL * DMODEL) / 4;
        split_bf16_kernel<<<o4 / 256, 256>>>(w_o, woh, wol, o4);
    }

    // 1) QKV projection (HMMA bf16x3): [4096,6144]
    hmma_gemm_kernel<<<dim3(QKVDIM / HBN, MROWS / HBM), 256, HSMEM>>>(
        xh, xl, wqh, wql, b_qkv, qkv, MROWS, QKVDIM, DMODEL);

    // 2) RoPE
    {
        int total = BATCH * SEQLEN * (NHEADS + NKV) * (HD / 2);
        rope_kernel<<<total / 256, 256>>>(qkv);
    }

    // 3) flash attention -> g_attn
    {
        const int smem = (64 * 128 + 64 * KS_STRIDE + 64 * 128 + 64 * PS_STRIDE) * 4;
        cudaFuncSetAttribute(flash_attn_kernel,
                             cudaFuncAttributeMaxDynamicSharedMemorySize, smem);
        flash_attn_kernel<<<dim3(SEQLEN / FBM, NHEADS, BATCH), 256, smem>>>(qkv, attn);
    }

    // 4) split attention output, then O projection (HMMA bf16x3)
    {
        int n4 = (MROWS * DMODEL) / 4;
        split_bf16_kernel<<<n4 / 256, 256>>>(attn, ah, al, n4);
    }
    hmma_gemm_kernel<<<dim3(DMODEL / HBN, MROWS / HBM), 256, HSMEM>>>(
        ah, al, woh, wol, b_o, out, MROWS, DMODEL, DMODEL);
}

// round 5
// speedup vs baseline: 2.4253x; 1.6525x over previous
#include <cuda_runtime.h>
#include <cuda_bf16.h>
#include <math.h>
#include <stdint.h>

// ---------------- problem constants ----------------
#define BATCH   2
#define SEQLEN  2048
#define DMODEL  4096
#define NHEADS  32
#define NKV     8
#define HD      128
#define QDIM    (NHEADS * HD)            // 4096
#define KVDIM   (NKV * HD)               // 1024
#define QKVDIM  (QDIM + 2 * KVDIM)       // 6144
#define MROWS   (BATCH * SEQLEN)         // 4096

// ---------------- scratch (device globals: allocation-free) ----------------
__device__ float g_qkv[(size_t)MROWS * QKVDIM];
__device__ __nv_bfloat16 g_xh[(size_t)MROWS * DMODEL];
__device__ __nv_bfloat16 g_xl[(size_t)MROWS * DMODEL];
__device__ __nv_bfloat16 g_wqkvh[(size_t)QKVDIM * DMODEL];
__device__ __nv_bfloat16 g_wqkvl[(size_t)QKVDIM * DMODEL];
__device__ __nv_bfloat16 g_woh[(size_t)DMODEL * DMODEL];
__device__ __nv_bfloat16 g_wol[(size_t)DMODEL * DMODEL];
__device__ __nv_bfloat16 g_ah[(size_t)MROWS * DMODEL];
__device__ __nv_bfloat16 g_al[(size_t)MROWS * DMODEL];
__device__ __nv_bfloat16 g_qh[(size_t)MROWS * QKVDIM];   // rope'd qkv hi
__device__ __nv_bfloat16 g_ql[(size_t)MROWS * QKVDIM];   // rope'd qkv lo

// ---------------- helpers ----------------
__device__ __forceinline__ uint32_t smem_to_u32(const void* smem_ptr) {
    uint32_t addr;
    asm("{ .reg .u64 tmp; cvta.to.shared.u64 tmp, %1; cvt.u32.u64 %0, tmp; }"
        : "=r"(addr) : "l"(smem_ptr));
    return addr;
}
__device__ __forceinline__ void cp_async16(uint32_t dst, const void* src) {
    asm volatile("cp.async.cg.shared.global [%0], [%1], 16;\n"
                 :: "r"(dst), "l"(src));
}
__device__ __forceinline__ void cp_commit() {
    asm volatile("cp.async.commit_group;\n" ::: "memory");
}
__device__ __forceinline__ void cp_wait1() {
    asm volatile("cp.async.wait_group 1;\n" ::: "memory");
}
__device__ __forceinline__ void ldm_x4(uint32_t* r, uint32_t a) {
    asm volatile("ldmatrix.sync.aligned.m8n8.x4.shared.b16 {%0,%1,%2,%3}, [%4];"
                 : "=r"(r[0]), "=r"(r[1]), "=r"(r[2]), "=r"(r[3]) : "r"(a));
}
__device__ __forceinline__ void ldm_x4_t(uint32_t* r, uint32_t a) {
    asm volatile("ldmatrix.sync.aligned.m8n8.x4.trans.shared.b16 {%0,%1,%2,%3}, [%4];"
                 : "=r"(r[0]), "=r"(r[1]), "=r"(r[2]), "=r"(r[3]) : "r"(a));
}
__device__ __forceinline__ void mma_bf16(float* c, const uint32_t* a,
                                         uint32_t b0, uint32_t b1) {
    asm volatile(
        "mma.sync.aligned.m16n8k16.row.col.f32.bf16.bf16.f32 "
        "{%0,%1,%2,%3}, {%4,%5,%6,%7}, {%8,%9}, {%0,%1,%2,%3};"
        : "+f"(c[0]), "+f"(c[1]), "+f"(c[2]), "+f"(c[3])
        : "r"(a[0]), "r"(a[1]), "r"(a[2]), "r"(a[3]), "r"(b0), "r"(b1));
}
__device__ __forceinline__ float ex2f(float x) {
    float y;
    asm("ex2.approx.f32 %0, %1;" : "=f"(y) : "f"(x));
    return y;
}
__device__ __forceinline__ uint32_t pack_bf16(float f0, float f1) {
    uint16_t b0 = __bfloat16_as_ushort(__float2bfloat16_rn(f0));
    uint16_t b1 = __bfloat16_as_ushort(__float2bfloat16_rn(f1));
    return ((uint32_t)b1 << 16) | (uint32_t)b0;
}

// ============================================================
// HMMA GEMM (unchanged from round 4, passing)
// ============================================================
#define HBM 128
#define HBN 256
#define HBK 32
#define ROWB 80
#define OFF_AH 0
#define OFF_AL 10240
#define OFF_BH 20480
#define OFF_BL 40960
#define STAGE_B 61440
#define HSMEM (2 * STAGE_B)

__device__ __forceinline__ void gemm_load_stage(
    const __nv_bfloat16* __restrict__ Ah, const __nv_bfloat16* __restrict__ Al,
    const __nv_bfloat16* __restrict__ Bh, const __nv_bfloat16* __restrict__ Bl,
    uint32_t sbase, int bm, int bn, int k0, int K, int tid)
{
    #pragma unroll
    for (int l = 0; l < 2; l++) {
        int u = tid + l * 256;
        int r = u >> 2, g = u & 3;
        size_t goff = (size_t)(bm + r) * K + k0 + g * 8;
        cp_async16(sbase + OFF_AH + r * ROWB + g * 16, Ah + goff);
        cp_async16(sbase + OFF_AL + r * ROWB + g * 16, Al + goff);
    }
    #pragma unroll
    for (int l = 0; l < 4; l++) {
        int u = tid + l * 256;
        int r = u >> 2, g = u & 3;
        size_t goff = (size_t)(bn + r) * K + k0 + g * 8;
        cp_async16(sbase + OFF_BH + r * ROWB + g * 16, Bh + goff);
        cp_async16(sbase + OFF_BL + r * ROWB + g * 16, Bl + goff);
    }
}

__global__ __launch_bounds__(256) void hmma_gemm_kernel(
    const __nv_bfloat16* __restrict__ Ah, const __nv_bfloat16* __restrict__ Al,
    const __nv_bfloat16* __restrict__ Bh, const __nv_bfloat16* __restrict__ Bl,
    const float* __restrict__ bias, float* __restrict__ C,
    int M, int N, int K)
{
    extern __shared__ char smem[];
    const uint32_t sb = smem_to_u32(smem);
    const int tid = threadIdx.x;
    const int lane = tid & 31, wid = tid >> 5;
    const int wm = wid & 1;
    const int wn = wid >> 1;
    const int bm = blockIdx.y * HBM;
    const int bn = blockIdx.x * HBN;

    float acc[4][8][4];
    #pragma unroll
    for (int i = 0; i < 4; i++)
        #pragma unroll
        for (int j = 0; j < 8; j++)
            #pragma unroll
            for (int v = 0; v < 4; v++) acc[i][j][v] = 0.f;

    const int NC = K / HBK;

    gemm_load_stage(Ah, Al, Bh, Bl, sb, bm, bn, 0, K, tid);
    cp_commit();

    for (int c = 0; c < NC; c++) {
        if (c + 1 < NC)
            gemm_load_stage(Ah, Al, Bh, Bl, sb + ((c + 1) & 1) * STAGE_B,
                            bm, bn, (c + 1) * HBK, K, tid);
        cp_commit();
        cp_wait1();
        __syncthreads();

        const uint32_t base = sb + (c & 1) * STAGE_B;
        #pragma unroll
        for (int ks = 0; ks < 2; ks++) {
            const int kb = ks * 32 + ((lane >> 4) * 16);
            uint32_t a_addr = base + OFF_AH + (wm * 64 + (lane & 15)) * ROWB + kb;
            uint32_t b_addr = base + OFF_BH + (wn * 64 + (lane & 15)) * ROWB + kb;

            uint32_t A0[4][4], A1[4][4], B0[4][4];
            #pragma unroll
            for (int mt = 0; mt < 4; mt++) ldm_x4(A0[mt], a_addr + mt * 16 * ROWB);
            #pragma unroll
            for (int nt = 0; nt < 4; nt++) ldm_x4(B0[nt], b_addr + nt * 16 * ROWB);

            #pragma unroll
            for (int mt = 0; mt < 4; mt++)
                #pragma unroll
                for (int nt = 0; nt < 4; nt++) {
                    mma_bf16(acc[mt][2 * nt],     A0[mt], B0[nt][0], B0[nt][2]);
                    mma_bf16(acc[mt][2 * nt + 1], A0[mt], B0[nt][1], B0[nt][3]);
                }
            #pragma unroll
            for (int mt = 0; mt < 4; mt++)
                ldm_x4(A1[mt], a_addr + (OFF_AL - OFF_AH) + mt * 16 * ROWB);
            #pragma unroll
            for (int mt = 0; mt < 4; mt++)
                #pragma unroll
                for (int nt = 0; nt < 4; nt++) {
                    mma_bf16(acc[mt][2 * nt],     A1[mt], B0[nt][0], B0[nt][2]);
                    mma_bf16(acc[mt][2 * nt + 1], A1[mt], B0[nt][1], B0[nt][3]);
                }
            #pragma unroll
            for (int nt = 0; nt < 4; nt++)
                ldm_x4(B0[nt], b_addr + (OFF_BL - OFF_BH) + nt * 16 * ROWB);
            #pragma unroll
            for (int mt = 0; mt < 4; mt++)
                #pragma unroll
                for (int nt = 0; nt < 4; nt++) {
                    mma_bf16(acc[mt][2 * nt],     A0[mt], B0[nt][0], B0[nt][2]);
                    mma_bf16(acc[mt][2 * nt + 1], A0[mt], B0[nt][1], B0[nt][3]);
                }
        }
        __syncthreads();
    }

    #pragma unroll
    for (int mt = 0; mt < 4; mt++) {
        const int row0 = bm + wm * 64 + mt * 16 + (lane >> 2);
        #pragma unroll
        for (int nt = 0; nt < 8; nt++) {
            const int col = bn + wn * 64 + nt * 8 + (lane & 3) * 2;
            const float b0 = bias[col], b1 = bias[col + 1];
            float2 v0 = make_float2(acc[mt][nt][0] + b0, acc[mt][nt][1] + b1);
            float2 v1 = make_float2(acc[mt][nt][2] + b0, acc[mt][nt][3] + b1);
            *(float2*)(C + (size_t)row0 * N + col) = v0;
            *(float2*)(C + (size_t)(row0 + 8) * N + col) = v1;
        }
    }
}

// ============================================================
// fp32 -> bf16 hi/lo split
// ============================================================
__global__ void split_bf16_kernel(const float* __restrict__ src,
                                  __nv_bfloat16* __restrict__ hi,
                                  __nv_bfloat16* __restrict__ lo, int n4)
{
    int i = blockIdx.x * blockDim.x + threadIdx.x;
    if (i >= n4) return;
    float4 v = ((const float4*)src)[i];
    __nv_bfloat16 h0 = __float2bfloat16(v.x);
    __nv_bfloat16 h1 = __float2bfloat16(v.y);
    __nv_bfloat16 h2 = __float2bfloat16(v.z);
    __nv_bfloat16 h3 = __float2bfloat16(v.w);
    __nv_bfloat16 l0 = __float2bfloat16(v.x - __bfloat162float(h0));
    __nv_bfloat16 l1 = __float2bfloat16(v.y - __bfloat162float(h1));
    __nv_bfloat16 l2 = __float2bfloat16(v.z - __bfloat162float(h2));
    __nv_bfloat16 l3 = __float2bfloat16(v.w - __bfloat162float(h3));
    __nv_bfloat162* hp = (__nv_bfloat162*)hi;
    __nv_bfloat162* lp = (__nv_bfloat162*)lo;
    hp[2 * i]     = __nv_bfloat162(h0, h1);
    hp[2 * i + 1] = __nv_bfloat162(h2, h3);
    lp[2 * i]     = __nv_bfloat162(l0, l1);
    lp[2 * i + 1] = __nv_bfloat162(l2, l3);
}

// ============================================================
// RoPE + hi/lo split of QKV: g_qkv(fp32) -> g_qh/g_ql (bf16)
// one thread per column pair.
// ============================================================
__global__ void rope_split_kernel(const float* __restrict__ qkv,
                                  __nv_bfloat16* __restrict__ oh,
                                  __nv_bfloat16* __restrict__ ol)
{
    int idx = blockIdx.x * blockDim.x + threadIdx.x;          // pair idx
    const int HP = QKVDIM / 2;
    int c2 = idx % HP;
    int rowi = idx / HP;
    if (rowi >= MROWS) return;
    int col = 2 * c2;
    int s = rowi & (SEQLEN - 1);

    float2 v = *(const float2*)(qkv + (size_t)rowi * QKVDIM + col);
    float r0 = v.x, r1 = v.y;

    if (col < QDIM + KVDIM) {  // rope applies to q and k regions
        int p = (col & 127) >> 1;
        float inv_freq = powf(10000.0f, -(float)(2 * p) / (float)HD);
        float ang = (float)s * inv_freq;
        float c, sn;
        sincosf(ang, &sn, &c);
        float xr = v.x, xi = v.y;
        r0 = xr * c - xi * sn;
        r1 = xr * sn + xi * c;
    }

    __nv_bfloat16 h0 = __float2bfloat16(r0);
    __nv_bfloat16 h1 = __float2bfloat16(r1);
    __nv_bfloat16 l0 = __float2bfloat16(r0 - __bfloat162float(h0));
    __nv_bfloat16 l1 = __float2bfloat16(r1 - __bfloat162float(h1));
    *(__nv_bfloat162*)(oh + (size_t)rowi * QKVDIM + col) = __nv_bfloat162(h0, h1);
    *(__nv_bfloat162*)(ol + (size_t)rowi * QKVDIM + col) = __nv_bfloat162(l0, l1);
}

// ============================================================
// HMMA flash attention: Br=128 (8 warps x 16 rows), Bc=64,
// bf16 hi/lo 3-pass for both QK^T and PV. Output -> bf16 hi/lo.
// ============================================================
#define QROWB 272             // 128 bf16 + 8 pad, bytes
#define FA_QH  0
#define FA_QL  34816
#define FA_ST0 69632          // stage base
#define FA_STB 69632          // bytes per stage (Kh,Kl,Vh,Vl)
#define FA_KH  0
#define FA_KL  17408
#define FA_VH  34816
#define FA_VL  52224
#define FA_SMEM (69632 + 2 * 69632)   // 208896

__global__ __launch_bounds__(256) void fa_hmma_kernel(
    const __nv_bfloat16* __restrict__ qh, const __nv_bfloat16* __restrict__ ql,
    __nv_bfloat16* __restrict__ oh, __nv_bfloat16* __restrict__ ol)
{
    extern __shared__ char smem[];
    const uint32_t sb = smem_to_u32(smem);
    const int tid = threadIdx.x;
    const int lane = tid & 31, w = tid >> 5;
    const int b = blockIdx.z, h = blockIdx.y, qb = blockIdx.x;
    const int kvh = h >> 2;
    const int q0 = qb * 128;
    const int rowbase = b * SEQLEN;

    // ---- load Q tile (hi+lo): 128 rows x 16 chunks x 2 = 4096 ----
    #pragma unroll
    for (int l = 0; l < 16; l++) {
        int u = tid + l * 256;
        int half = u >> 11;
        int r = (u >> 4) & 127;
        int ch = u & 15;
        const __nv_bfloat16* src = (half ? ql : qh) +
            (size_t)(rowbase + q0 + r) * QKVDIM + h * HD + ch * 8;
        cp_async16(sb + (half ? FA_QL : FA_QH) + r * QROWB + ch * 16, src);
    }
    // ---- kv stage loader ----
    auto load_kv = [&](int t, int s) {
        const int k0 = t * 64;
        const uint32_t stb = sb + FA_ST0 + s * FA_STB;
        #pragma unroll
        for (int l = 0; l < 16; l++) {
            int u = tid + l * 256;
            int sel = u >> 10;            // 0 Kh, 1 Kl, 2 Vh, 3 Vl
            int r = (u >> 4) & 63;
            int ch = u & 15;
            int gcol = (sel < 2) ? (QDIM + kvh * HD) : (QDIM + KVDIM + kvh * HD);
            const __nv_bfloat16* base = (sel & 1) ? ql : qh;
            const __nv_bfloat16* src = base +
                (size_t)(rowbase + k0 + r) * QKVDIM + gcol + ch * 8;
            cp_async16(stb + sel * 17408 + r * QROWB + ch * 16, src);
        }
    };

    const int tmax = 2 * qb + 2;
    load_kv(0, 0);
    cp_commit();

    const float CEXP = 0.12751742f;       // (1/sqrt(128)) * log2(e)
    float m2[2] = {-1e30f, -1e30f};
    float l2[2] = {0.f, 0.f};
    float O[16][4];
    #pragma unroll
    for (int i = 0; i < 16; i++)
        #pragma unroll
        for (int v = 0; v < 4; v++) O[i][v] = 0.f;

    const int qrow0 = q0 + w * 16;

    for (int t = 0; t < tmax; t++) {
        if (t + 1 < tmax) load_kv(t + 1, (t + 1) & 1);
        cp_commit();
        cp_wait1();
        __syncthreads();

        const int k0 = t * 64;
        const uint32_t stb = sb + FA_ST0 + (t & 1) * FA_STB;

        if (k0 <= qrow0 + 15) {   // warp has at least one unmasked element
            // ---------- scores S = Q K^T (bf16x3) ----------
            float S[8][4];
            #pragma unroll
            for (int i = 0; i < 8; i++)
                #pragma unroll
                for (int v = 0; v < 4; v++) S[i][v] = 0.f;

            const uint32_t qa = sb + FA_QH + (w * 16 + (lane & 15)) * QROWB +
                                ((lane >> 4) * 16);
            const uint32_t ka = stb + FA_KH + ((lane & 15)) * QROWB +
                                ((lane >> 4) * 16);
            #pragma unroll
            for (int kc = 0; kc < 8; kc++) {
                uint32_t A0[4], A1[4];
                ldm_x4(A0, qa + kc * 32);
                ldm_x4(A1, qa + kc * 32 + (FA_QL - FA_QH));
                #pragma unroll
                for (int g = 0; g < 4; g++) {
                    uint32_t B[4];
                    ldm_x4(B, ka + kc * 32 + g * 16 * QROWB);
                    mma_bf16(S[2 * g],     A0, B[0], B[2]);
                    mma_bf16(S[2 * g + 1], A0, B[1], B[3]);
                    mma_bf16(S[2 * g],     A1, B[0], B[2]);
                    mma_bf16(S[2 * g + 1], A1, B[1], B[3]);
                    ldm_x4(B, ka + kc * 32 + 17408 + g * 16 * QROWB);
                    mma_bf16(S[2 * g],     A0, B[0], B[2]);
                    mma_bf16(S[2 * g + 1], A0, B[1], B[3]);
                }
            }

            // ---------- causal mask ----------
            if (k0 + 63 > qrow0) {
                const int r0 = qrow0 + (lane >> 2);
                #pragma unroll
                for (int nt = 0; nt < 8; nt++) {
                    const int c0 = k0 + nt * 8 + (lane & 3) * 2;
                    if (c0     > r0)     S[nt][0] = -1e30f;
                    if (c0 + 1 > r0)     S[nt][1] = -1e30f;
                    if (c0     > r0 + 8) S[nt][2] = -1e30f;
                    if (c0 + 1 > r0 + 8) S[nt][3] = -1e30f;
                }
            }

            // ---------- online softmax ----------
            #pragma unroll
            for (int r = 0; r < 2; r++) {
                const int i0 = r * 2;
                float rmax = -1e30f;
                #pragma unroll
                for (int nt = 0; nt < 8; nt++)
                    rmax = fmaxf(rmax, fmaxf(S[nt][i0], S[nt][i0 + 1]));
                rmax = fmaxf(rmax, __shfl_xor_sync(0xffffffffu, rmax, 1));
                rmax = fmaxf(rmax, __shfl_xor_sync(0xffffffffu, rmax, 2));
                const float mnew = fmaxf(m2[r], rmax);
                const float corr = ex2f((m2[r] - mnew) * CEXP);
                m2[r] = mnew;
                float psum = 0.f;
                #pragma unroll
                for (int nt = 0; nt < 8; nt++) {
                    float p0 = ex2f((S[nt][i0]     - mnew) * CEXP);
                    float p1 = ex2f((S[nt][i0 + 1] - mnew) * CEXP);
                    S[nt][i0] = p0; S[nt][i0 + 1] = p1;
                    psum += p0 + p1;
                }
                psum += __shfl_xor_sync(0xffffffffu, psum, 1);
                psum += __shfl_xor_sync(0xffffffffu, psum, 2);
                l2[r] = l2[r] * corr + psum;
                #pragma unroll
                for (int nt = 0; nt < 16; nt++) {
                    O[nt][i0]     *= corr;
                    O[nt][i0 + 1] *= corr;
                }
            }

            // ---------- PV (bf16x3) ----------
            #pragma unroll
            for (int j = 0; j < 4; j++) {
                uint32_t Ph[4], Pl[4];
                #pragma unroll
                for (int q = 0; q < 2; q++) {        // two n-tiles -> k halves
                    const int nt = 2 * j + q;
                    #pragma unroll
                    for (int rr = 0; rr < 2; rr++) {
                        float f0 = S[nt][2 * rr], f1 = S[nt][2 * rr + 1];
                        uint32_t hi = pack_bf16(f0, f1);
                        float g0 = f0 - __bfloat162float(__float2bfloat16_rn(f0));
                        float g1 = f1 - __bfloat162float(__float2bfloat16_rn(f1));
                        uint32_t loo = pack_bf16(g0, g1);
                        Ph[2 * q + rr] = hi;
                        Pl[2 * q + rr] = loo;
                    }
                }
                const int vrow = j * 16 + (lane & 7) + ((lane >> 3) & 1) * 8;
                #pragma unroll
                for (int n = 0; n < 8; n++) {
                    uint32_t va = stb + FA_VH + vrow * QROWB +
                                  (n * 16 + (lane >> 4) * 8) * 2;
                    uint32_t Bv[4];
                    ldm_x4_t(Bv, va);
                    mma_bf16(O[2 * n],     Ph, Bv[0], Bv[1]);
                    mma_bf16(O[2 * n + 1], Ph, Bv[2], Bv[3]);
                    mma_bf16(O[2 * n],     Pl, Bv[0], Bv[1]);
                    mma_bf16(O[2 * n + 1], Pl, Bv[2], Bv[3]);
                    ldm_x4_t(Bv, va + (FA_VL - FA_VH));
                    mma_bf16(O[2 * n],     Ph, Bv[0], Bv[1]);
                    mma_bf16(O[2 * n + 1], Ph, Bv[2], Bv[3]);
                }
            }
        }
        __syncthreads();
    }

    // ---------- epilogue: normalize, split to bf16 hi/lo ----------
    #pragma unroll
    for (int r = 0; r < 2; r++) {
        float inv = 1.0f / l2[r];
        const int row = rowbase + qrow0 + (lane >> 2) + r * 8;
        const size_t off = (size_t)row * DMODEL + h * HD + (lane & 3) * 2;
        #pragma unroll
        for (int nt = 0; nt < 16; nt++) {
            float f0 = O[nt][2 * r] * inv;
            float f1 = O[nt][2 * r + 1] * inv;
            uint32_t hi = pack_bf16(f0, f1);
            float g0 = f0 - __bfloat162float(__float2bfloat16_rn(f0));
            float g1 = f1 - __bfloat162float(__float2bfloat16_rn(f1));
            uint32_t lo = pack_bf16(g0, g1);
            *(uint32_t*)(oh + off + nt * 8) = hi;
            *(uint32_t*)(ol + off + nt * 8) = lo;
        }
    }
}

// ============================================================
// launch
// ============================================================
extern "C" void kernel_launch(void* const* d_in, const int* in_sizes, int n_in,
                              void* d_out, int out_size)
{
    (void)in_sizes; (void)n_in; (void)out_size;
    const float* x      = (const float*)d_in[0];
    const float* w_qkv  = (const float*)d_in[1];
    const float* b_qkv  = (const float*)d_in[2];
    const float* w_o    = (const float*)d_in[3];
    const float* b_o    = (const float*)d_in[4];
    float* out = (float*)d_out;

    float *qkv;
    __nv_bfloat16 *xh, *xl, *wqh, *wql, *woh, *wol, *ah, *al, *qh, *ql;
    cudaGetSymbolAddress((void**)&qkv, g_qkv);
    cudaGetSymbolAddress((void**)&xh,  g_xh);
    cudaGetSymbolAddress((void**)&xl,  g_xl);
    cudaGetSymbolAddress((void**)&wqh, g_wqkvh);
    cudaGetSymbolAddress((void**)&wql, g_wqkvl);
    cudaGetSymbolAddress((void**)&woh, g_woh);
    cudaGetSymbolAddress((void**)&wol, g_wol);
    cudaGetSymbolAddress((void**)&ah,  g_ah);
    cudaGetSymbolAddress((void**)&al,  g_al);
    cudaGetSymbolAddress((void**)&qh,  g_qh);
    cudaGetSymbolAddress((void**)&ql,  g_ql);

    cudaFuncSetAttribute(hmma_gemm_kernel,
                         cudaFuncAttributeMaxDynamicSharedMemorySize, HSMEM);
    cudaFuncSetAttribute(fa_hmma_kernel,
                         cudaFuncAttributeMaxDynamicSharedMemorySize, FA_SMEM);

    // 0) split inputs to bf16 hi/lo
    {
        int n4 = (MROWS * DMODEL) / 4;
        split_bf16_kernel<<<n4 / 256, 256>>>(x, xh, xl, n4);
        int w4 = (QKVDIM * DMODEL) / 4;
        split_bf16_kernel<<<w4 / 256, 256>>>(w_qkv, wqh, wql, w4);
        int o4 = (DMODEL * DMODEL) / 4;
        split_bf16_kernel<<<o4 / 256, 256>>>(w_o, woh, wol, o4);
    }

    // 1) QKV projection (HMMA bf16x3) -> fp32 g_qkv
    hmma_gemm_kernel<<<dim3(QKVDIM / HBN, MROWS / HBM), 256, HSMEM>>>(
        xh, xl, wqh, wql, b_qkv, qkv, MROWS, QKVDIM, DMODEL);

    // 2) RoPE + split to bf16 hi/lo
    {
        int pairs = MROWS * (QKVDIM / 2);
        rope_split_kernel<<<pairs / 256, 256>>>(qkv, qh, ql);
    }

    // 3) HMMA flash attention -> g_ah/g_al (bf16 hi/lo)
    fa_hmma_kernel<<<dim3(SEQLEN / 128, NHEADS, BATCH), 256, FA_SMEM>>>(
        qh, ql, ah, al);

    // 4) O projection (HMMA bf16x3)
    hmma_gemm_kernel<<<dim3(DMODEL / HBN, MROWS / HBM), 256, HSMEM>>>(
        ah, al, woh, wol, b_o, out, MROWS, DMODEL, DMODEL);
}

// round 6
// speedup vs baseline: 2.4354x; 1.0042x over previous
#include <cuda_runtime.h>
#include <cuda_bf16.h>
#include <math.h>
#include <stdint.h>

// ---------------- problem constants ----------------
#define BATCH   2
#define SEQLEN  2048
#define DMODEL  4096
#define NHEADS  32
#define NKV     8
#define HD      128
#define QDIM    (NHEADS * HD)            // 4096
#define KVDIM   (NKV * HD)               // 1024
#define QKVDIM  (QDIM + 2 * KVDIM)       // 6144
#define MROWS   (BATCH * SEQLEN)         // 4096

// ---------------- scratch (device globals: allocation-free) ----------------
__device__ float g_qkv[(size_t)MROWS * QKVDIM];
__device__ __nv_bfloat16 g_xh[(size_t)MROWS * DMODEL];
__device__ __nv_bfloat16 g_xl[(size_t)MROWS * DMODEL];
__device__ __nv_bfloat16 g_wqkvh[(size_t)QKVDIM * DMODEL];
__device__ __nv_bfloat16 g_wqkvl[(size_t)QKVDIM * DMODEL];
__device__ __nv_bfloat16 g_woh[(size_t)DMODEL * DMODEL];
__device__ __nv_bfloat16 g_wol[(size_t)DMODEL * DMODEL];
__device__ __nv_bfloat16 g_ah[(size_t)MROWS * DMODEL];
__device__ __nv_bfloat16 g_al[(size_t)MROWS * DMODEL];
__device__ __nv_bfloat16 g_qh[(size_t)MROWS * QKVDIM];
__device__ __nv_bfloat16 g_ql[(size_t)MROWS * QKVDIM];

// ---------------- helpers ----------------
__device__ __forceinline__ uint32_t smem_to_u32(const void* smem_ptr) {
    uint32_t addr;
    asm("{ .reg .u64 tmp; cvta.to.shared.u64 tmp, %1; cvt.u32.u64 %0, tmp; }"
        : "=r"(addr) : "l"(smem_ptr));
    return addr;
}
__device__ __forceinline__ void cp_async16(uint32_t dst, const void* src) {
    asm volatile("cp.async.cg.shared.global [%0], [%1], 16;\n"
                 :: "r"(dst), "l"(src));
}
__device__ __forceinline__ void cp_commit() {
    asm volatile("cp.async.commit_group;\n" ::: "memory");
}
__device__ __forceinline__ void cp_wait1() {
    asm volatile("cp.async.wait_group 1;\n" ::: "memory");
}
__device__ __forceinline__ void cp_wait2() {
    asm volatile("cp.async.wait_group 2;\n" ::: "memory");
}
__device__ __forceinline__ void ldm_x4(uint32_t* r, uint32_t a) {
    asm volatile("ldmatrix.sync.aligned.m8n8.x4.shared.b16 {%0,%1,%2,%3}, [%4];"
                 : "=r"(r[0]), "=r"(r[1]), "=r"(r[2]), "=r"(r[3]) : "r"(a));
}
__device__ __forceinline__ void ldm_x4_t(uint32_t* r, uint32_t a) {
    asm volatile("ldmatrix.sync.aligned.m8n8.x4.trans.shared.b16 {%0,%1,%2,%3}, [%4];"
                 : "=r"(r[0]), "=r"(r[1]), "=r"(r[2]), "=r"(r[3]) : "r"(a));
}
__device__ __forceinline__ void mma_bf16(float* c, const uint32_t* a,
                                         uint32_t b0, uint32_t b1) {
    asm volatile(
        "mma.sync.aligned.m16n8k16.row.col.f32.bf16.bf16.f32 "
        "{%0,%1,%2,%3}, {%4,%5,%6,%7}, {%8,%9}, {%0,%1,%2,%3};"
        : "+f"(c[0]), "+f"(c[1]), "+f"(c[2]), "+f"(c[3])
        : "r"(a[0]), "r"(a[1]), "r"(a[2]), "r"(a[3]), "r"(b0), "r"(b1));
}
__device__ __forceinline__ float ex2f(float x) {
    float y;
    asm("ex2.approx.f32 %0, %1;" : "=f"(y) : "f"(x));
    return y;
}
__device__ __forceinline__ uint32_t pack_bf16(float f0, float f1) {
    uint16_t b0 = __bfloat16_as_ushort(__float2bfloat16_rn(f0));
    uint16_t b1 = __bfloat16_as_ushort(__float2bfloat16_rn(f1));
    return ((uint32_t)b1 << 16) | (uint32_t)b0;
}

// ============================================================
// HMMA GEMM v2: 512 threads (16 warps, warp tile 64x32),
// CTA tile 128x256, BK=32, 3-stage cp.async pipeline,
// bf16x3 emulation, fp32 accum.
// ============================================================
#define HBM 128
#define HBN 256
#define HBK 32
#define ROWB 80
#define OFF_AH 0
#define OFF_AL 10240
#define OFF_BH 20480
#define OFF_BL 40960
#define STAGE_B 61440
#define HSMEM (3 * STAGE_B)      // 184320 bytes

__device__ __forceinline__ void gemm_load_stage(
    const __nv_bfloat16* __restrict__ Ah, const __nv_bfloat16* __restrict__ Al,
    const __nv_bfloat16* __restrict__ Bh, const __nv_bfloat16* __restrict__ Bl,
    uint32_t sbase, int bm, int bn, int k0, int K, int tid)
{
    // A: 128 rows x 4 chunks x 2 halves = 1024 chunks; 512 threads -> 2 iters
    #pragma unroll
    for (int l = 0; l < 2; l++) {
        int u = tid + l * 512;
        int half = u >> 9;
        int r = (u >> 2) & 127, g = u & 3;
        size_t goff = (size_t)(bm + r) * K + k0 + g * 8;
        cp_async16(sbase + (half ? OFF_AL : OFF_AH) + r * ROWB + g * 16,
                   (half ? Al : Ah) + goff);
    }
    // B: 256 rows x 4 chunks x 2 halves = 2048 chunks; -> 4 iters
    #pragma unroll
    for (int l = 0; l < 4; l++) {
        int u = tid + l * 512;
        int half = u >> 10;
        int r = (u >> 2) & 255, g = u & 3;
        size_t goff = (size_t)(bn + r) * K + k0 + g * 8;
        cp_async16(sbase + (half ? OFF_BL : OFF_BH) + r * ROWB + g * 16,
                   (half ? Bl : Bh) + goff);
    }
}

__global__ __launch_bounds__(512, 1) void hmma_gemm_kernel(
    const __nv_bfloat16* __restrict__ Ah, const __nv_bfloat16* __restrict__ Al,
    const __nv_bfloat16* __restrict__ Bh, const __nv_bfloat16* __restrict__ Bl,
    const float* __restrict__ bias, float* __restrict__ C,
    int M, int N, int K)
{
    extern __shared__ char smem[];
    const uint32_t sb = smem_to_u32(smem);
    const int tid = threadIdx.x;
    const int lane = tid & 31, wid = tid >> 5;
    const int wm = wid & 1;        // 2 warp rows (64 m each)
    const int wn = wid >> 1;       // 8 warp cols (32 n each)
    const int bm = blockIdx.y * HBM;
    const int bn = blockIdx.x * HBN;

    float acc[4][4][4];
    #pragma unroll
    for (int i = 0; i < 4; i++)
        #pragma unroll
        for (int j = 0; j < 4; j++)
            #pragma unroll
            for (int v = 0; v < 4; v++) acc[i][j][v] = 0.f;

    const int NC = K / HBK;

    gemm_load_stage(Ah, Al, Bh, Bl, sb, bm, bn, 0, K, tid);
    cp_commit();
    gemm_load_stage(Ah, Al, Bh, Bl, sb + STAGE_B, bm, bn, HBK, K, tid);
    cp_commit();

    int st = 0;   // stage index of chunk c
    for (int c = 0; c < NC; c++) {
        if (c + 2 < NC) {
            int st2 = st + 2; if (st2 >= 3) st2 -= 3;
            gemm_load_stage(Ah, Al, Bh, Bl, sb + st2 * STAGE_B,
                            bm, bn, (c + 2) * HBK, K, tid);
        }
        cp_commit();
        cp_wait2();
        __syncthreads();

        const uint32_t base = sb + st * STAGE_B;
        #pragma unroll
        for (int ks = 0; ks < 2; ks++) {
            const int kb = ks * 32 + ((lane >> 4) * 16);
            uint32_t a_addr = base + OFF_AH + (wm * 64 + (lane & 15)) * ROWB + kb;
            uint32_t b_addr = base + OFF_BH + (wn * 32 + (lane & 15)) * ROWB + kb;

            uint32_t A0[4][4], A1[4][4], B0[2][4];
            #pragma unroll
            for (int mt = 0; mt < 4; mt++) ldm_x4(A0[mt], a_addr + mt * 16 * ROWB);
            #pragma unroll
            for (int nb = 0; nb < 2; nb++) ldm_x4(B0[nb], b_addr + nb * 16 * ROWB);

            // pass 1: Ah * Bh
            #pragma unroll
            for (int mt = 0; mt < 4; mt++)
                #pragma unroll
                for (int nb = 0; nb < 2; nb++) {
                    mma_bf16(acc[mt][2 * nb],     A0[mt], B0[nb][0], B0[nb][2]);
                    mma_bf16(acc[mt][2 * nb + 1], A0[mt], B0[nb][1], B0[nb][3]);
                }
            // pass 2: Al * Bh
            #pragma unroll
            for (int mt = 0; mt < 4; mt++)
                ldm_x4(A1[mt], a_addr + (OFF_AL - OFF_AH) + mt * 16 * ROWB);
            #pragma unroll
            for (int mt = 0; mt < 4; mt++)
                #pragma unroll
                for (int nb = 0; nb < 2; nb++) {
                    mma_bf16(acc[mt][2 * nb],     A1[mt], B0[nb][0], B0[nb][2]);
                    mma_bf16(acc[mt][2 * nb + 1], A1[mt], B0[nb][1], B0[nb][3]);
                }
            // pass 3: Ah * Bl
            #pragma unroll
            for (int nb = 0; nb < 2; nb++)
                ldm_x4(B0[nb], b_addr + (OFF_BL - OFF_BH) + nb * 16 * ROWB);
            #pragma unroll
            for (int mt = 0; mt < 4; mt++)
                #pragma unroll
                for (int nb = 0; nb < 2; nb++) {
                    mma_bf16(acc[mt][2 * nb],     A0[mt], B0[nb][0], B0[nb][2]);
                    mma_bf16(acc[mt][2 * nb + 1], A0[mt], B0[nb][1], B0[nb][3]);
                }
        }
        __syncthreads();
        if (++st == 3) st = 0;
    }

    // epilogue: fused bias, float2 stores
    #pragma unroll
    for (int mt = 0; mt < 4; mt++) {
        const int row0 = bm + wm * 64 + mt * 16 + (lane >> 2);
        #pragma unroll
        for (int nt = 0; nt < 4; nt++) {
            const int col = bn + wn * 32 + nt * 8 + (lane & 3) * 2;
            const float b0 = bias[col], b1 = bias[col + 1];
            float2 v0 = make_float2(acc[mt][nt][0] + b0, acc[mt][nt][1] + b1);
            float2 v1 = make_float2(acc[mt][nt][2] + b0, acc[mt][nt][3] + b1);
            *(float2*)(C + (size_t)row0 * N + col) = v0;
            *(float2*)(C + (size_t)(row0 + 8) * N + col) = v1;
        }
    }
}

// ============================================================
// fp32 -> bf16 hi/lo split (for x, weights)
// ============================================================
__global__ void split_bf16_kernel(const float* __restrict__ src,
                                  __nv_bfloat16* __restrict__ hi,
                                  __nv_bfloat16* __restrict__ lo, int n4)
{
    int i = blockIdx.x * blockDim.x + threadIdx.x;
    if (i >= n4) return;
    float4 v = ((const float4*)src)[i];
    __nv_bfloat16 h0 = __float2bfloat16(v.x);
    __nv_bfloat16 h1 = __float2bfloat16(v.y);
    __nv_bfloat16 h2 = __float2bfloat16(v.z);
    __nv_bfloat16 h3 = __float2bfloat16(v.w);
    __nv_bfloat16 l0 = __float2bfloat16(v.x - __bfloat162float(h0));
    __nv_bfloat16 l1 = __float2bfloat16(v.y - __bfloat162float(h1));
    __nv_bfloat16 l2 = __float2bfloat16(v.z - __bfloat162float(h2));
    __nv_bfloat16 l3 = __float2bfloat16(v.w - __bfloat162float(h3));
    __nv_bfloat162* hp = (__nv_bfloat162*)hi;
    __nv_bfloat162* lp = (__nv_bfloat162*)lo;
    hp[2 * i]     = __nv_bfloat162(h0, h1);
    hp[2 * i + 1] = __nv_bfloat162(h2, h3);
    lp[2 * i]     = __nv_bfloat162(l0, l1);
    lp[2 * i + 1] = __nv_bfloat162(l2, l3);
}

// ============================================================
// RoPE+split on q/k: one thread per (row, freq-pair) -> 40 heads
// ============================================================
__global__ void rope_split_qk_kernel(const float* __restrict__ qkv,
                                     __nv_bfloat16* __restrict__ oh,
                                     __nv_bfloat16* __restrict__ ol)
{
    int idx = blockIdx.x * blockDim.x + threadIdx.x;   // MROWS*64
    int p = idx & 63;
    int rowi = idx >> 6;
    if (rowi >= MROWS) return;
    int s = rowi & (SEQLEN - 1);

    float inv_freq = powf(10000.0f, -(float)(2 * p) / (float)HD);
    float ang = (float)s * inv_freq;
    float c, sn;
    sincosf(ang, &sn, &c);

    const float* row = qkv + (size_t)rowi * QKVDIM;
    __nv_bfloat16* ohr = oh + (size_t)rowi * QKVDIM;
    __nv_bfloat16* olr = ol + (size_t)rowi * QKVDIM;

    #pragma unroll 4
    for (int hh = 0; hh < NHEADS + NKV; hh++) {
        int col = ((hh < NHEADS) ? hh * HD : QDIM + (hh - NHEADS) * HD) + 2 * p;
        float2 v = *(const float2*)(row + col);
        float r0 = v.x * c - v.y * sn;
        float r1 = v.x * sn + v.y * c;
        __nv_bfloat16 h0 = __float2bfloat16(r0);
        __nv_bfloat16 h1 = __float2bfloat16(r1);
        __nv_bfloat16 l0 = __float2bfloat16(r0 - __bfloat162float(h0));
        __nv_bfloat16 l1 = __float2bfloat16(r1 - __bfloat162float(h1));
        *(__nv_bfloat162*)(ohr + col) = __nv_bfloat162(h0, h1);
        *(__nv_bfloat162*)(olr + col) = __nv_bfloat162(l0, l1);
    }
}

// split-only for V region (cols QDIM+KVDIM .. QKVDIM)
__global__ void split_v_kernel(const float* __restrict__ qkv,
                               __nv_bfloat16* __restrict__ oh,
                               __nv_bfloat16* __restrict__ ol)
{
    int idx = blockIdx.x * blockDim.x + threadIdx.x;   // MROWS*512 pairs
    int c2 = idx & 511;
    int rowi = idx >> 9;
    if (rowi >= MROWS) return;
    size_t off = (size_t)rowi * QKVDIM + QDIM + KVDIM + 2 * c2;
    float2 v = *(const float2*)(g_qkv + off);
    (void)qkv;
    __nv_bfloat16 h0 = __float2bfloat16(v.x);
    __nv_bfloat16 h1 = __float2bfloat16(v.y);
    __nv_bfloat16 l0 = __float2bfloat16(v.x - __bfloat162float(h0));
    __nv_bfloat16 l1 = __float2bfloat16(v.y - __bfloat162float(h1));
    *(__nv_bfloat162*)(oh + off) = __nv_bfloat162(h0, h1);
    *(__nv_bfloat162*)(ol + off) = __nv_bfloat162(l0, l1);
}

// ============================================================
// HMMA flash attention (unchanged from round 5, passing):
// Br=128 (8 warps x 16 rows), Bc=64, bf16x3 for QK^T and PV.
// ============================================================
#define QROWB 272
#define FA_QH  0
#define FA_QL  34816
#define FA_ST0 69632
#define FA_STB 69632
#define FA_KH  0
#define FA_KL  17408
#define FA_VH  34816
#define FA_VL  52224
#define FA_SMEM (69632 + 2 * 69632)

__global__ __launch_bounds__(256) void fa_hmma_kernel(
    const __nv_bfloat16* __restrict__ qh, const __nv_bfloat16* __restrict__ ql,
    __nv_bfloat16* __restrict__ oh, __nv_bfloat16* __restrict__ ol)
{
    extern __shared__ char smem[];
    const uint32_t sb = smem_to_u32(smem);
    const int tid = threadIdx.x;
    const int lane = tid & 31, w = tid >> 5;
    const int b = blockIdx.z, h = blockIdx.y, qb = blockIdx.x;
    const int kvh = h >> 2;
    const int q0 = qb * 128;
    const int rowbase = b * SEQLEN;

    #pragma unroll
    for (int l = 0; l < 16; l++) {
        int u = tid + l * 256;
        int half = u >> 11;
        int r = (u >> 4) & 127;
        int ch = u & 15;
        const __nv_bfloat16* src = (half ? ql : qh) +
            (size_t)(rowbase + q0 + r) * QKVDIM + h * HD + ch * 8;
        cp_async16(sb + (half ? FA_QL : FA_QH) + r * QROWB + ch * 16, src);
    }
    auto load_kv = [&](int t, int s) {
        const int k0 = t * 64;
        const uint32_t stb = sb + FA_ST0 + s * FA_STB;
        #pragma unroll
        for (int l = 0; l < 16; l++) {
            int u = tid + l * 256;
            int sel = u >> 10;
            int r = (u >> 4) & 63;
            int ch = u & 15;
            int gcol = (sel < 2) ? (QDIM + kvh * HD) : (QDIM + KVDIM + kvh * HD);
            const __nv_bfloat16* base = (sel & 1) ? ql : qh;
            const __nv_bfloat16* src = base +
                (size_t)(rowbase + k0 + r) * QKVDIM + gcol + ch * 8;
            cp_async16(stb + sel * 17408 + r * QROWB + ch * 16, src);
        }
    };

    const int tmax = 2 * qb + 2;
    load_kv(0, 0);
    cp_commit();

    const float CEXP = 0.12751742f;
    float m2[2] = {-1e30f, -1e30f};
    float l2[2] = {0.f, 0.f};
    float O[16][4];
    #pragma unroll
    for (int i = 0; i < 16; i++)
        #pragma unroll
        for (int v = 0; v < 4; v++) O[i][v] = 0.f;

    const int qrow0 = q0 + w * 16;

    for (int t = 0; t < tmax; t++) {
        if (t + 1 < tmax) load_kv(t + 1, (t + 1) & 1);
        cp_commit();
        cp_wait1();
        __syncthreads();

        const int k0 = t * 64;
        const uint32_t stb = sb + FA_ST0 + (t & 1) * FA_STB;

        if (k0 <= qrow0 + 15) {
            float S[8][4];
            #pragma unroll
            for (int i = 0; i < 8; i++)
                #pragma unroll
                for (int v = 0; v < 4; v++) S[i][v] = 0.f;

            const uint32_t qa = sb + FA_QH + (w * 16 + (lane & 15)) * QROWB +
                                ((lane >> 4) * 16);
            const uint32_t ka = stb + FA_KH + ((lane & 15)) * QROWB +
                                ((lane >> 4) * 16);
            #pragma unroll
            for (int kc = 0; kc < 8; kc++) {
                uint32_t A0[4], A1[4];
                ldm_x4(A0, qa + kc * 32);
                ldm_x4(A1, qa + kc * 32 + (FA_QL - FA_QH));
                #pragma unroll
                for (int g = 0; g < 4; g++) {
                    uint32_t B[4];
                    ldm_x4(B, ka + kc * 32 + g * 16 * QROWB);
                    mma_bf16(S[2 * g],     A0, B[0], B[2]);
                    mma_bf16(S[2 * g + 1], A0, B[1], B[3]);
                    mma_bf16(S[2 * g],     A1, B[0], B[2]);
                    mma_bf16(S[2 * g + 1], A1, B[1], B[3]);
                    ldm_x4(B, ka + kc * 32 + 17408 + g * 16 * QROWB);
                    mma_bf16(S[2 * g],     A0, B[0], B[2]);
                    mma_bf16(S[2 * g + 1], A0, B[1], B[3]);
                }
            }

            if (k0 + 63 > qrow0) {
                const int r0 = qrow0 + (lane >> 2);
                #pragma unroll
                for (int nt = 0; nt < 8; nt++) {
                    const int c0 = k0 + nt * 8 + (lane & 3) * 2;
                    if (c0     > r0)     S[nt][0] = -1e30f;
                    if (c0 + 1 > r0)     S[nt][1] = -1e30f;
                    if (c0     > r0 + 8) S[nt][2] = -1e30f;
                    if (c0 + 1 > r0 + 8) S[nt][3] = -1e30f;
                }
            }

            #pragma unroll
            for (int r = 0; r < 2; r++) {
                const int i0 = r * 2;
                float rmax = -1e30f;
                #pragma unroll
                for (int nt = 0; nt < 8; nt++)
                    rmax = fmaxf(rmax, fmaxf(S[nt][i0], S[nt][i0 + 1]));
                rmax = fmaxf(rmax, __shfl_xor_sync(0xffffffffu, rmax, 1));
                rmax = fmaxf(rmax, __shfl_xor_sync(0xffffffffu, rmax, 2));
                const float mnew = fmaxf(m2[r], rmax);
                const float corr = ex2f((m2[r] - mnew) * CEXP);
                m2[r] = mnew;
                float psum = 0.f;
                #pragma unroll
                for (int nt = 0; nt < 8; nt++) {
                    float p0 = ex2f((S[nt][i0]     - mnew) * CEXP);
                    float p1 = ex2f((S[nt][i0 + 1] - mnew) * CEXP);
                    S[nt][i0] = p0; S[nt][i0 + 1] = p1;
                    psum += p0 + p1;
                }
                psum += __shfl_xor_sync(0xffffffffu, psum, 1);
                psum += __shfl_xor_sync(0xffffffffu, psum, 2);
                l2[r] = l2[r] * corr + psum;
                #pragma unroll
                for (int nt = 0; nt < 16; nt++) {
                    O[nt][i0]     *= corr;
                    O[nt][i0 + 1] *= corr;
                }
            }

            #pragma unroll
            for (int j = 0; j < 4; j++) {
                uint32_t Ph[4], Pl[4];
                #pragma unroll
                for (int q = 0; q < 2; q++) {
                    const int nt = 2 * j + q;
                    #pragma unroll
                    for (int rr = 0; rr < 2; rr++) {
                        float f0 = S[nt][2 * rr], f1 = S[nt][2 * rr + 1];
                        uint32_t hi = pack_bf16(f0, f1);
                        float g0 = f0 - __bfloat162float(__float2bfloat16_rn(f0));
                        float g1 = f1 - __bfloat162float(__float2bfloat16_rn(f1));
                        uint32_t loo = pack_bf16(g0, g1);
                        Ph[2 * q + rr] = hi;
                        Pl[2 * q + rr] = loo;
                    }
                }
                const int vrow = j * 16 + (lane & 7) + ((lane >> 3) & 1) * 8;
                #pragma unroll
                for (int n = 0; n < 8; n++) {
                    uint32_t va = stb + FA_VH + vrow * QROWB +
                                  (n * 16 + (lane >> 4) * 8) * 2;
                    uint32_t Bv[4];
                    ldm_x4_t(Bv, va);
                    mma_bf16(O[2 * n],     Ph, Bv[0], Bv[1]);
                    mma_bf16(O[2 * n + 1], Ph, Bv[2], Bv[3]);
                    mma_bf16(O[2 * n],     Pl, Bv[0], Bv[1]);
                    mma_bf16(O[2 * n + 1], Pl, Bv[2], Bv[3]);
                    ldm_x4_t(Bv, va + (FA_VL - FA_VH));
                    mma_bf16(O[2 * n],     Ph, Bv[0], Bv[1]);
                    mma_bf16(O[2 * n + 1], Ph, Bv[2], Bv[3]);
                }
            }
        }
        __syncthreads();
    }

    #pragma unroll
    for (int r = 0; r < 2; r++) {
        float inv = 1.0f / l2[r];
        const int row = rowbase + qrow0 + (lane >> 2) + r * 8;
        const size_t off = (size_t)row * DMODEL + h * HD + (lane & 3) * 2;
        #pragma unroll
        for (int nt = 0; nt < 16; nt++) {
            float f0 = O[nt][2 * r] * inv;
            float f1 = O[nt][2 * r + 1] * inv;
            uint32_t hi = pack_bf16(f0, f1);
            float g0 = f0 - __bfloat162float(__float2bfloat16_rn(f0));
            float g1 = f1 - __bfloat162float(__float2bfloat16_rn(f1));
            uint32_t lo = pack_bf16(g0, g1);
            *(uint32_t*)(oh + off + nt * 8) = hi;
            *(uint32_t*)(ol + off + nt * 8) = lo;
        }
    }
}

// ============================================================
// launch
// ============================================================
extern "C" void kernel_launch(void* const* d_in, const int* in_sizes, int n_in,
                              void* d_out, int out_size)
{
    (void)in_sizes; (void)n_in; (void)out_size;
    const float* x      = (const float*)d_in[0];
    const float* w_qkv  = (const float*)d_in[1];
    const float* b_qkv  = (const float*)d_in[2];
    const float* w_o    = (const float*)d_in[3];
    const float* b_o    = (const float*)d_in[4];
    float* out = (float*)d_out;

    float *qkv;
    __nv_bfloat16 *xh, *xl, *wqh, *wql, *woh, *wol, *ah, *al, *qh, *ql;
    cudaGetSymbolAddress((void**)&qkv, g_qkv);
    cudaGetSymbolAddress((void**)&xh,  g_xh);
    cudaGetSymbolAddress((void**)&xl,  g_xl);
    cudaGetSymbolAddress((void**)&wqh, g_wqkvh);
    cudaGetSymbolAddress((void**)&wql, g_wqkvl);
    cudaGetSymbolAddress((void**)&woh, g_woh);
    cudaGetSymbolAddress((void**)&wol, g_wol);
    cudaGetSymbolAddress((void**)&ah,  g_ah);
    cudaGetSymbolAddress((void**)&al,  g_al);
    cudaGetSymbolAddress((void**)&qh,  g_qh);
    cudaGetSymbolAddress((void**)&ql,  g_ql);

    cudaFuncSetAttribute(hmma_gemm_kernel,
                         cudaFuncAttributeMaxDynamicSharedMemorySize, HSMEM);
    cudaFuncSetAttribute(fa_hmma_kernel,
                         cudaFuncAttributeMaxDynamicSharedMemorySize, FA_SMEM);

    // 0) split inputs to bf16 hi/lo
    {
        int n4 = (MROWS * DMODEL) / 4;
        split_bf16_kernel<<<n4 / 256, 256>>>(x, xh, xl, n4);
        int w4 = (QKVDIM * DMODEL) / 4;
        split_bf16_kernel<<<w4 / 256, 256>>>(w_qkv, wqh, wql, w4);
        int o4 = (DMODEL * DMODEL) / 4;
        split_bf16_kernel<<<o4 / 256, 256>>>(w_o, woh, wol, o4);
    }

    // 1) QKV projection (HMMA bf16x3) -> fp32 g_qkv
    hmma_gemm_kernel<<<dim3(QKVDIM / HBN, MROWS / HBM), 512, HSMEM>>>(
        xh, xl, wqh, wql, b_qkv, qkv, MROWS, QKVDIM, DMODEL);

    // 2) RoPE + split to bf16 hi/lo
    rope_split_qk_kernel<<<(MROWS * 64) / 256, 256>>>(qkv, qh, ql);
    split_v_kernel<<<(MROWS * 512) / 256, 256>>>(qkv, qh, ql);

    // 3) HMMA flash attention -> g_ah/g_al (bf16 hi/lo)
    fa_hmma_kernel<<<dim3(SEQLEN / 128, NHEADS, BATCH), 256, FA_SMEM>>>(
        qh, ql, ah, al);

    // 4) O projection (HMMA bf16x3)
    hmma_gemm_kernel<<<dim3(DMODEL / HBN, MROWS / HBM), 512, HSMEM>>>(
        ah, al, woh, wol, b_o, out, MROWS, DMODEL, DMODEL);
}